// round 8
// baseline (speedup 1.0000x reference)
#include <cuda_runtime.h>
#include <cstdint>

#define BB   512      // batch
#define LL   512      // leaves
#define EE   128      // emb
#define OPS  5
#define NI   511      // internal nodes
#define RPC  4        // batch rows per CTA

typedef unsigned long long ull;

// scratch: all node embeddings [B][NI][E]  (~134 MB)
__device__ float g_nodes[(size_t)BB * NI * EE];

// ---------------- packed f32x2 helpers ----------------
__device__ __forceinline__ ull pack2(float lo, float hi) {
    ull r;
    asm("mov.b64 %0, {%1, %2};" : "=l"(r) : "f"(lo), "f"(hi));
    return r;
}
__device__ __forceinline__ void fma2(ull& d, ull a, ull b) {
    asm("fma.rn.f32x2 %0, %1, %2, %0;" : "+l"(d) : "l"(a), "l"(b));
}
__device__ __forceinline__ ull add2(ull a, ull b) {
    ull r;
    asm("add.rn.f32x2 %0, %1, %2;" : "=l"(r) : "l"(a), "l"(b));
    return r;
}
__device__ __forceinline__ float2 unpack2(ull v) {
    float2 f;
    asm("mov.b64 {%0, %1}, %2;" : "=f"(f.x), "=f"(f.y) : "l"(v));
    return f;
}
__device__ __forceinline__ ull shfl_xor64(ull v, int m) {
    return __shfl_xor_sync(0xFFFFFFFFu, v, m);
}

// ---------------- sequential recurrence ----------------
// 256 threads: h = t&7 (K eighth, 16B chunks at float index 4h+32i, i=0..3),
// cg = t>>3 (0..31). Thread computes 4 output cols {cg, cg+32, cg+64, cg+96};
// each 16B x-load feeds 8 FFMA2 -> 32 LDS.128/thread/step (L1 wavefronts ==
// FMA pipe floor). Warp phase lanes h=0..7 read one contiguous 128B line.
// Reduction over 8 h-lanes: 3 packed-b64 shuffle stages; commit split across
// lanes h==r (cols cg,cg+32) and h==r+4 (cols cg+64,cg+96).
__global__ void __launch_bounds__(256, 1) recur_kernel(
    const float* __restrict__ emb,   // [B, L, E]
    const float* __restrict__ Ww,    // [2E, E]
    const float* __restrict__ Wb,    // [E]
    const int*   __restrict__ li,    // [NI]
    const int*   __restrict__ ri)    // [NI]
{
    __shared__ __align__(16) float cur[2][RPC][EE];    // double-buffered state
    __shared__ __align__(16) float leafs[2][RPC][EE];  // double-buffered right leaf
    __shared__ int ridx[NI + 1];

    const int t  = threadIdx.x;
    const int h  = t & 7;           // K-slice
    const int cg = t >> 3;          // 0..31
    const int b0 = blockIdx.x * RPC;

    // Weight slices: 2 sides x 4 cols x 16 K-floats = 64 b64 (128 regs).
    ull w[2][4][8];
#pragma unroll
    for (int side = 0; side < 2; side++) {
#pragma unroll
        for (int i = 0; i < 4; i++) {
            const int k0 = side * 128 + 4 * h + 32 * i;
#pragma unroll
            for (int c = 0; c < 4; c++) {
                const int n = cg + 32 * c;
                w[side][c][2*i]   = pack2(Ww[(size_t)(k0    ) * EE + n], Ww[(size_t)(k0 + 1) * EE + n]);
                w[side][c][2*i+1] = pack2(Ww[(size_t)(k0 + 2) * EE + n], Ww[(size_t)(k0 + 3) * EE + n]);
            }
        }
    }
    const ull bias01 = pack2(Wb[cg],      Wb[cg + 32]);
    const ull bias23 = pack2(Wb[cg + 64], Wb[cg + 96]);

    // right-leaf indices into smem
    for (int j = t; j < NI; j += 256) ridx[j] = ri[j];
    if (t == 0) ridx[NI] = ri[0];   // dummy for prefetch overrun

    // init cur[0] = leaf(left_idx[0]); loader: 4 rows x 64 lanes x float2
    const int l0   = li[0];
    const int r_ld = t >> 6;
    const int c_ld = (t & 63) * 2;
    {
        const float2 v = *(const float2*)&emb[((size_t)(b0 + r_ld) * LL + l0) * EE + c_ld];
        cur[0][r_ld][c_ld]     = v.x;
        cur[0][r_ld][c_ld + 1] = v.y;
    }
    __syncthreads();

    // prefetch right leaf for step 0
    float2 lv = *(const float2*)&emb[((size_t)(b0 + r_ld) * LL + ridx[0]) * EE + c_ld];

    for (int j = 0; j < NI; j++) {
        const int rb = j & 1;           // read state buffer
        const int wbuf = rb ^ 1;        // write state buffer
        // commit prefetched leaf; one barrier covers leaf-ready + prev cur writes
        leafs[rb][r_ld][c_ld]     = lv.x;
        leafs[rb][r_ld][c_ld + 1] = lv.y;
        const int rnext = ridx[j + 1];
        __syncthreads();
        lv = *(const float2*)&emb[((size_t)(b0 + r_ld) * LL + rnext) * EE + c_ld];

#pragma unroll
        for (int r = 0; r < RPC; r++) {
            ull s0[4] = {0ull, 0ull, 0ull, 0ull};
            ull s1[4] = {0ull, 0ull, 0ull, 0ull};
            const ulonglong2* xl = (const ulonglong2*)cur[rb][r];
            const ulonglong2* xr = (const ulonglong2*)leafs[rb][r];
#pragma unroll
            for (int i = 0; i < 4; i++) {
                const ulonglong2 p = xl[h + 8 * i];
#pragma unroll
                for (int c = 0; c < 4; c++) {
                    fma2(s0[c], p.x, w[0][c][2*i]);
                    fma2(s1[c], p.y, w[0][c][2*i+1]);
                }
            }
#pragma unroll
            for (int i = 0; i < 4; i++) {
                const ulonglong2 p = xr[h + 8 * i];
#pragma unroll
                for (int c = 0; c < 4; c++) {
                    fma2(s0[c], p.x, w[1][c][2*i]);
                    fma2(s1[c], p.y, w[1][c][2*i+1]);
                }
            }
            // horizontal per col, then across the 8 h-lanes (packed b64 shuffles)
            float v[4];
#pragma unroll
            for (int c = 0; c < 4; c++) {
                const float2 f = unpack2(add2(s0[c], s1[c]));
                v[c] = f.x + f.y;
            }
            ull u01 = pack2(v[0], v[1]);
            ull u23 = pack2(v[2], v[3]);
            u01 = add2(u01, shfl_xor64(u01, 1));
            u23 = add2(u23, shfl_xor64(u23, 1));
            u01 = add2(u01, shfl_xor64(u01, 2));
            u23 = add2(u23, shfl_xor64(u23, 2));
            u01 = add2(u01, shfl_xor64(u01, 4));
            u23 = add2(u23, shfl_xor64(u23, 4));   // all 8 h-lanes hold row sums
            if (h == r) {
                const float2 y = unpack2(add2(u01, bias01));
                cur[wbuf][r][cg]      = y.x;
                cur[wbuf][r][cg + 32] = y.y;
                float* gn = &g_nodes[((size_t)(b0 + r) * NI + j) * EE];
                gn[cg]      = y.x;
                gn[cg + 32] = y.y;
            }
            if (h == r + 4) {
                const float2 y = unpack2(add2(u23, bias23));
                cur[wbuf][r][cg + 64] = y.x;
                cur[wbuf][r][cg + 96] = y.y;
                float* gn = &g_nodes[((size_t)(b0 + r) * NI + j) * EE];
                gn[cg + 64] = y.x;
                gn[cg + 96] = y.y;
            }
        }
    }
}

// ---------------- parallel projection: op = node @ G_w + G_b ----------------
// 2 nodes per warp (2 outstanding LDG.128 -> DRAM latency shared)
__global__ void __launch_bounds__(256) proj_kernel(
    const float* __restrict__ Gw,   // [E, OPS]
    const float* __restrict__ Gb,   // [OPS]
    float* __restrict__ out,        // [B, NI, OPS]
    int total_pairs)
{
    __shared__ float gws[EE * OPS];
    __shared__ float gbs[OPS];
    const int t = threadIdx.x;
    for (int i = t; i < EE * OPS; i += blockDim.x) gws[i] = Gw[i];
    if (t < OPS) gbs[t] = Gb[t];
    __syncthreads();

    const int pair = blockIdx.x * (blockDim.x >> 5) + (t >> 5);
    if (pair >= total_pairs) return;
    const int lane  = t & 31;
    const size_t n0 = (size_t)pair * 2;

    const float4 x0 = *(const float4*)&g_nodes[n0 * EE + lane * 4];
    const float4 x1 = *(const float4*)&g_nodes[(n0 + 1) * EE + lane * 4];
    const float* g  = &gws[lane * 4 * OPS];

    float p0[OPS], p1[OPS];
#pragma unroll
    for (int o = 0; o < OPS; o++) {
        p0[o] = x0.x * g[o] + x0.y * g[OPS + o] + x0.z * g[2 * OPS + o] + x0.w * g[3 * OPS + o];
        p1[o] = x1.x * g[o] + x1.y * g[OPS + o] + x1.z * g[2 * OPS + o] + x1.w * g[3 * OPS + o];
    }
#pragma unroll
    for (int off = 16; off; off >>= 1)
#pragma unroll
        for (int o = 0; o < OPS; o++) {
            p0[o] += __shfl_xor_sync(0xFFFFFFFFu, p0[o], off);
            p1[o] += __shfl_xor_sync(0xFFFFFFFFu, p1[o], off);
        }

    if (lane == 0) {
        float* op = out + n0 * OPS;
#pragma unroll
        for (int o = 0; o < OPS; o++) { op[o] = p0[o] + gbs[o]; op[OPS + o] = p1[o] + gbs[o]; }
    }
}

// ---------------- labels tail ----------------
// Labels land on device as int32 (JAX x64 disabled). mode 1: float cast.
// mode 2: widen to raw int64.
__global__ void tail_kernel(const int* __restrict__ labels, float* __restrict__ out, int mode)
{
    const int j = blockIdx.x * blockDim.x + threadIdx.x;
    if (j >= NI) return;
    const size_t base = (size_t)BB * NI * OPS;
    if (mode == 1) {
        out[base + j] = (float)labels[j];
    } else {
        ((long long*)(out + base))[j] = (long long)labels[j];
    }
}

extern "C" void kernel_launch(void* const* d_in, const int* in_sizes, int n_in,
                              void* d_out, int out_size)
{
    const float* emb    = (const float*)d_in[0];
    const float* Ww     = (const float*)d_in[1];
    const float* Wb     = (const float*)d_in[2];
    const float* Gw     = (const float*)d_in[3];
    const float* Gb     = (const float*)d_in[4];
    const int*   li     = (const int*)d_in[5];
    const int*   ri     = (const int*)d_in[6];
    const int*   labels = (const int*)d_in[7];
    float*       out    = (float*)d_out;

    recur_kernel<<<BB / RPC, 256>>>(emb, Ww, Wb, li, ri);

    const int total_pairs = BB * NI / 2;                    // 130816
    proj_kernel<<<total_pairs / 8, 256>>>(Gw, Gb, out, total_pairs); // 8 warps/block

    const long long base = (long long)BB * NI * OPS;
    const long long tail = (long long)out_size - base;
    if (tail == NI)          tail_kernel<<<2, 256>>>(labels, out, 1);
    else if (tail == 2 * NI) tail_kernel<<<2, 256>>>(labels, out, 2);
}

// round 9
// speedup vs baseline: 1.0194x; 1.0194x over previous
#include <cuda_runtime.h>
#include <cstdint>

#define BB   512      // batch
#define LL   512      // leaves
#define EE   128      // emb
#define OPS  5
#define NI   511      // internal nodes
#define RPC  4        // batch rows per CTA

typedef unsigned long long ull;

// scratch: all node embeddings [B][NI][E]  (~134 MB)
__device__ float g_nodes[(size_t)BB * NI * EE];

// ---------------- packed f32x2 helpers ----------------
__device__ __forceinline__ ull pack2(float lo, float hi) {
    ull r;
    asm("mov.b64 %0, {%1, %2};" : "=l"(r) : "f"(lo), "f"(hi));
    return r;
}
__device__ __forceinline__ void fma2(ull& d, ull a, ull b) {
    asm("fma.rn.f32x2 %0, %1, %2, %0;" : "+l"(d) : "l"(a), "l"(b));
}
__device__ __forceinline__ ull add2(ull a, ull b) {
    ull r;
    asm("add.rn.f32x2 %0, %1, %2;" : "=l"(r) : "l"(a), "l"(b));
    return r;
}
__device__ __forceinline__ float2 unpack2(ull v) {
    float2 f;
    asm("mov.b64 {%0, %1}, %2;" : "=f"(f.x), "=f"(f.y) : "l"(v));
    return f;
}

// ---------------- sequential recurrence ----------------
// 256 threads: h = t&1 (K half, interleaved 16B chunks), n = t>>1 (0..127).
// Thread computes ONE output column n over 64+64 K-floats (chunks h+2i,
// i=0..15, per side). Same compute stream as the 671us champion (64 LDS.128,
// 256 fma2 per thread per step) but the K-half partner is the adjacent lane:
// reduction = 1 shfl_xor(1), ONE barrier per step, no smem red round-trip.
// Each lane commits rows {h, h+2}. Leaf prefetch distance = 2 steps.
__global__ void __launch_bounds__(256, 1) recur_kernel(
    const float* __restrict__ emb,   // [B, L, E]
    const float* __restrict__ Ww,    // [2E, E]
    const float* __restrict__ Wb,    // [E]
    const int*   __restrict__ li,    // [NI]
    const int*   __restrict__ ri)    // [NI]
{
    __shared__ __align__(16) float cur[2][RPC][EE];    // double-buffered state
    __shared__ __align__(16) float leafs[2][RPC][EE];  // double-buffered right leaf
    __shared__ int ridx[NI + 2];

    const int t  = threadIdx.x;
    const int h  = t & 1;           // K-half
    const int n  = t >> 1;          // output column 0..127
    const int b0 = blockIdx.x * RPC;

    // Weight slices: 2 sides x 64 K-floats = 64 b64 (128 regs).
    // Chunk i of half h covers floats k = 4*(h + 2i) .. +3.
    ull wl[32], wr[32];
#pragma unroll
    for (int i = 0; i < 16; i++) {
        const int k0 = 4 * (h + 2 * i);
        wl[2*i]   = pack2(Ww[(size_t)(k0    ) * EE + n], Ww[(size_t)(k0 + 1) * EE + n]);
        wl[2*i+1] = pack2(Ww[(size_t)(k0 + 2) * EE + n], Ww[(size_t)(k0 + 3) * EE + n]);
        wr[2*i]   = pack2(Ww[(size_t)(EE + k0    ) * EE + n], Ww[(size_t)(EE + k0 + 1) * EE + n]);
        wr[2*i+1] = pack2(Ww[(size_t)(EE + k0 + 2) * EE + n], Ww[(size_t)(EE + k0 + 3) * EE + n]);
    }
    const float biasv = Wb[n];

    // right-leaf indices into smem (with 2 dummies for prefetch overrun)
    for (int j = t; j < NI; j += 256) ridx[j] = ri[j];
    if (t == 0) { ridx[NI] = ri[0]; ridx[NI + 1] = ri[0]; }

    // init cur[0] = leaf(left_idx[0]); loader: 4 rows x 64 lanes x float2
    const int l0   = li[0];
    const int r_ld = t >> 6;
    const int c_ld = (t & 63) * 2;
    {
        const float2 v = *(const float2*)&emb[((size_t)(b0 + r_ld) * LL + l0) * EE + c_ld];
        cur[0][r_ld][c_ld]     = v.x;
        cur[0][r_ld][c_ld + 1] = v.y;
    }
    __syncthreads();

    // prefetch right leaves for steps 0 and 1 (distance-2 pipeline)
    float2 lv0 = *(const float2*)&emb[((size_t)(b0 + r_ld) * LL + ridx[0]) * EE + c_ld];
    float2 lv1 = *(const float2*)&emb[((size_t)(b0 + r_ld) * LL + ridx[1]) * EE + c_ld];

    for (int j = 0; j < NI; j++) {
        const int rb = j & 1;           // read state buffer
        const int wbuf = rb ^ 1;        // write state buffer
        // commit leaf for this step; one barrier covers leaf + prev cur writes
        leafs[rb][r_ld][c_ld]     = lv0.x;
        leafs[rb][r_ld][c_ld + 1] = lv0.y;
        const int rnext = ridx[j + 2];
        __syncthreads();
        lv0 = lv1;      // leaf for step j+1 (already in flight / landed)
        lv1 = *(const float2*)&emb[((size_t)(b0 + r_ld) * LL + rnext) * EE + c_ld];

#pragma unroll
        for (int r = 0; r < RPC; r++) {
            ull s0 = 0ull, s1 = 0ull;
            const ulonglong2* xl = (const ulonglong2*)cur[rb][r];
            const ulonglong2* xr = (const ulonglong2*)leafs[rb][r];
#pragma unroll
            for (int i = 0; i < 16; i++) {
                const ulonglong2 p = xl[h + 2 * i];
                fma2(s0, p.x, wl[2*i]);
                fma2(s1, p.y, wl[2*i+1]);
            }
#pragma unroll
            for (int i = 0; i < 16; i++) {
                const ulonglong2 p = xr[h + 2 * i];
                fma2(s0, p.x, wr[2*i]);
                fma2(s1, p.y, wr[2*i+1]);
            }
            // horizontal, then across the lane pair (partner = t^1, same warp)
            const float2 f = unpack2(add2(s0, s1));
            float u = f.x + f.y;
            u += __shfl_xor_sync(0xFFFFFFFFu, u, 1);   // both h-lanes hold y[r][n]
            if ((r & 1) == h) {                         // lane commits rows h, h+2
                const float v = u + biasv;
                cur[wbuf][r][n] = v;
                g_nodes[((size_t)(b0 + r) * NI + j) * EE + n] = v;
            }
        }
    }
}

// ---------------- parallel projection: op = node @ G_w + G_b ----------------
// 4 nodes per warp (4 outstanding LDG.128 -> DRAM latency shared)
__global__ void __launch_bounds__(256) proj_kernel(
    const float* __restrict__ Gw,   // [E, OPS]
    const float* __restrict__ Gb,   // [OPS]
    float* __restrict__ out,        // [B, NI, OPS]
    int total_quads)
{
    __shared__ float gws[EE * OPS];
    __shared__ float gbs[OPS];
    const int t = threadIdx.x;
    for (int i = t; i < EE * OPS; i += blockDim.x) gws[i] = Gw[i];
    if (t < OPS) gbs[t] = Gb[t];
    __syncthreads();

    const int quad = blockIdx.x * (blockDim.x >> 5) + (t >> 5);
    if (quad >= total_quads) return;
    const int lane  = t & 31;
    const size_t n0 = (size_t)quad * 4;

    float4 x[4];
#pragma unroll
    for (int q = 0; q < 4; q++)
        x[q] = *(const float4*)&g_nodes[(n0 + q) * EE + lane * 4];
    const float* g = &gws[lane * 4 * OPS];

    float p[4][OPS];
#pragma unroll
    for (int q = 0; q < 4; q++)
#pragma unroll
        for (int o = 0; o < OPS; o++)
            p[q][o] = x[q].x * g[o] + x[q].y * g[OPS + o]
                    + x[q].z * g[2 * OPS + o] + x[q].w * g[3 * OPS + o];

#pragma unroll
    for (int off = 16; off; off >>= 1)
#pragma unroll
        for (int q = 0; q < 4; q++)
#pragma unroll
            for (int o = 0; o < OPS; o++)
                p[q][o] += __shfl_xor_sync(0xFFFFFFFFu, p[q][o], off);

    if (lane == 0) {
        float* op = out + n0 * OPS;
#pragma unroll
        for (int q = 0; q < 4; q++)
#pragma unroll
            for (int o = 0; o < OPS; o++)
                op[q * OPS + o] = p[q][o] + gbs[o];
    }
}

// ---------------- labels tail ----------------
// Labels land on device as int32 (JAX x64 disabled). mode 1: float cast.
// mode 2: widen to raw int64.
__global__ void tail_kernel(const int* __restrict__ labels, float* __restrict__ out, int mode)
{
    const int j = blockIdx.x * blockDim.x + threadIdx.x;
    if (j >= NI) return;
    const size_t base = (size_t)BB * NI * OPS;
    if (mode == 1) {
        out[base + j] = (float)labels[j];
    } else {
        ((long long*)(out + base))[j] = (long long)labels[j];
    }
}

extern "C" void kernel_launch(void* const* d_in, const int* in_sizes, int n_in,
                              void* d_out, int out_size)
{
    const float* emb    = (const float*)d_in[0];
    const float* Ww     = (const float*)d_in[1];
    const float* Wb     = (const float*)d_in[2];
    const float* Gw     = (const float*)d_in[3];
    const float* Gb     = (const float*)d_in[4];
    const int*   li     = (const int*)d_in[5];
    const int*   ri     = (const int*)d_in[6];
    const int*   labels = (const int*)d_in[7];
    float*       out    = (float*)d_out;

    recur_kernel<<<BB / RPC, 256>>>(emb, Ww, Wb, li, ri);

    const int total_quads = BB * NI / 4;                   // 65408
    proj_kernel<<<total_quads / 8, 256>>>(Gw, Gb, out, total_quads); // 8 warps/block

    const long long base = (long long)BB * NI * OPS;
    const long long tail = (long long)out_size - base;
    if (tail == NI)          tail_kernel<<<2, 256>>>(labels, out, 1);
    else if (tail == 2 * NI) tail_kernel<<<2, 256>>>(labels, out, 2);
}

// round 10
// speedup vs baseline: 1.2934x; 1.2688x over previous
#include <cuda_runtime.h>
#include <cstdint>

#define BB   512      // batch
#define LL   512      // leaves
#define EE   128      // emb
#define OPS  5
#define NI   511      // internal nodes
#define RPC  4        // batch rows per CTA

typedef unsigned long long ull;

// scratch: all node embeddings [B][NI][E]  (~134 MB)
__device__ float g_nodes[(size_t)BB * NI * EE];

// ---------------- packed f32x2 helpers ----------------
__device__ __forceinline__ ull pack2(float lo, float hi) {
    ull r;
    asm("mov.b64 %0, {%1, %2};" : "=l"(r) : "f"(lo), "f"(hi));
    return r;
}
__device__ __forceinline__ void fma2(ull& d, ull a, ull b) {
    asm("fma.rn.f32x2 %0, %1, %2, %0;" : "+l"(d) : "l"(a), "l"(b));
}
__device__ __forceinline__ ull add2(ull a, ull b) {
    ull r;
    asm("add.rn.f32x2 %0, %1, %2;" : "=l"(r) : "l"(a), "l"(b));
    return r;
}
__device__ __forceinline__ float2 unpack2(ull v) {
    float2 f;
    asm("mov.b64 {%0, %1}, %2;" : "=f"(f.x), "=f"(f.y) : "l"(v));
    return f;
}

// ---------------- sequential recurrence ----------------
// Warp-sliced broadcast layout. 256 threads = 8 warps.
// Warp w owns K-slice 32w..32w+31 of the 256-float concat [cur | leaf]
// (warps 0-3 read cur, warps 4-7 read leaf). Lane l owns output columns
// {l, l+32, l+64, l+96}. All 32 lanes read the SAME 16B x-chunk ->
// broadcast = 1 L1 wavefront per LDS.128 (vs 4 for lane-replicated reads).
// Per thread per row: 8 LDS.128-bcast + 64 fma2. Cross-warp reduction via
// smem red[8][RPC][EE] (the empirically-best R2 pattern), 2 barriers/step.
__global__ void __launch_bounds__(256, 1) recur_kernel(
    const float* __restrict__ emb,   // [B, L, E]
    const float* __restrict__ Ww,    // [2E, E]
    const float* __restrict__ Wb,    // [E]
    const int*   __restrict__ li,    // [NI]
    const int*   __restrict__ ri)    // [NI]
{
    __shared__ __align__(16) float cur[2][RPC][EE];    // double-buffered state
    __shared__ __align__(16) float leafs[2][RPC][EE];  // double-buffered right leaf
    __shared__ __align__(16) float red[8][RPC][EE];    // per-warp partials (16 KB)
    __shared__ int ridx[NI + 1];

    const int t    = threadIdx.x;
    const int wid  = t >> 5;        // warp = K-slice 0..7
    const int lane = t & 31;
    const int b0   = blockIdx.x * RPC;

    // Weight slice: K-rows 32*wid..+31 (of 2E), cols lane+32c. 64 b64 regs.
    ull w[4][16];
#pragma unroll
    for (int c = 0; c < 4; c++) {
        const int n = lane + 32 * c;
#pragma unroll
        for (int i = 0; i < 16; i++) {
            const int k = 32 * wid + 2 * i;
            w[c][i] = pack2(Ww[(size_t)k * EE + n], Ww[(size_t)(k + 1) * EE + n]);
        }
    }
    // reduce-phase ownership: thread commits (rrow, rcol) and (rrow+2, rcol)
    const int   rcol  = t & 127;
    const int   rrow  = t >> 7;     // 0..1
    const float biasv = Wb[rcol];

    // right-leaf indices into smem
    for (int j = t; j < NI; j += 256) ridx[j] = ri[j];
    if (t == 0) ridx[NI] = ri[0];   // dummy for prefetch overrun

    // init cur[0] = leaf(left_idx[0]); loader: 4 rows x 64 lanes x float2
    const int l0   = li[0];
    const int r_ld = t >> 6;
    const int c_ld = (t & 63) * 2;
    {
        const float2 v = *(const float2*)&emb[((size_t)(b0 + r_ld) * LL + l0) * EE + c_ld];
        cur[0][r_ld][c_ld]     = v.x;
        cur[0][r_ld][c_ld + 1] = v.y;
    }
    __syncthreads();

    // prefetch right leaf for step 0
    float2 lv = *(const float2*)&emb[((size_t)(b0 + r_ld) * LL + ridx[0]) * EE + c_ld];

    for (int j = 0; j < NI; j++) {
        const int rb   = j & 1;         // read state buffer
        const int wbuf = rb ^ 1;        // write state buffer
        // commit prefetched leaf; barrier 1 covers leaf + prev cur commits
        leafs[rb][r_ld][c_ld]     = lv.x;
        leafs[rb][r_ld][c_ld + 1] = lv.y;
        const int rnext = ridx[j + 1];
        __syncthreads();
        lv = *(const float2*)&emb[((size_t)(b0 + r_ld) * LL + rnext) * EE + c_ld];

        // ---- phase A: per-warp K-slice partials, broadcast x reads ----
#pragma unroll
        for (int r = 0; r < RPC; r++) {
            // warp-uniform slice pointer (warps 0-3: cur, 4-7: leaf)
            const ulonglong2* xs = (wid < 4)
                ? (const ulonglong2*)&cur[rb][r][wid * 32]
                : (const ulonglong2*)&leafs[rb][r][(wid - 4) * 32];
            ull a0[4] = {0ull, 0ull, 0ull, 0ull};
            ull a1[4] = {0ull, 0ull, 0ull, 0ull};
#pragma unroll
            for (int jj = 0; jj < 8; jj++) {
                const ulonglong2 p = xs[jj];        // broadcast: 1 wavefront
#pragma unroll
                for (int c = 0; c < 4; c++) {
                    fma2(a0[c], p.x, w[c][2*jj]);
                    fma2(a1[c], p.y, w[c][2*jj+1]);
                }
            }
#pragma unroll
            for (int c = 0; c < 4; c++) {
                const float2 f = unpack2(add2(a0[c], a1[c]));
                red[wid][r][lane + 32 * c] = f.x + f.y;   // contiguous per warp
            }
        }
        __syncthreads();                 // barrier 2: partials ready

        // ---- phase B: reduce 8 slices, commit 2 outputs per thread ----
#pragma unroll
        for (int o = 0; o < 2; o++) {
            const int r = rrow + 2 * o;
            float s = red[0][r][rcol];
#pragma unroll
            for (int sl = 1; sl < 8; sl++) s += red[sl][r][rcol];
            const float v = s + biasv;
            cur[wbuf][r][rcol] = v;
            g_nodes[((size_t)(b0 + r) * NI + j) * EE + rcol] = v;
        }
        // next iteration's barrier 1 orders cur[wbuf] commits vs reads
    }
}

// ---------------- parallel projection: op = node @ G_w + G_b ----------------
// 4 nodes per warp (4 outstanding LDG.128 -> DRAM latency shared)
__global__ void __launch_bounds__(256) proj_kernel(
    const float* __restrict__ Gw,   // [E, OPS]
    const float* __restrict__ Gb,   // [OPS]
    float* __restrict__ out,        // [B, NI, OPS]
    int total_quads)
{
    __shared__ float gws[EE * OPS];
    __shared__ float gbs[OPS];
    const int t = threadIdx.x;
    for (int i = t; i < EE * OPS; i += blockDim.x) gws[i] = Gw[i];
    if (t < OPS) gbs[t] = Gb[t];
    __syncthreads();

    const int quad = blockIdx.x * (blockDim.x >> 5) + (t >> 5);
    if (quad >= total_quads) return;
    const int lane  = t & 31;
    const size_t n0 = (size_t)quad * 4;

    float4 x[4];
#pragma unroll
    for (int q = 0; q < 4; q++)
        x[q] = *(const float4*)&g_nodes[(n0 + q) * EE + lane * 4];
    const float* g = &gws[lane * 4 * OPS];

    float p[4][OPS];
#pragma unroll
    for (int q = 0; q < 4; q++)
#pragma unroll
        for (int o = 0; o < OPS; o++)
            p[q][o] = x[q].x * g[o] + x[q].y * g[OPS + o]
                    + x[q].z * g[2 * OPS + o] + x[q].w * g[3 * OPS + o];

#pragma unroll
    for (int off = 16; off; off >>= 1)
#pragma unroll
        for (int q = 0; q < 4; q++)
#pragma unroll
            for (int o = 0; o < OPS; o++)
                p[q][o] += __shfl_xor_sync(0xFFFFFFFFu, p[q][o], off);

    if (lane == 0) {
        float* op = out + n0 * OPS;
#pragma unroll
        for (int q = 0; q < 4; q++)
#pragma unroll
            for (int o = 0; o < OPS; o++)
                op[q * OPS + o] = p[q][o] + gbs[o];
    }
}

// ---------------- labels tail ----------------
// Labels land on device as int32 (JAX x64 disabled). mode 1: float cast.
// mode 2: widen to raw int64.
__global__ void tail_kernel(const int* __restrict__ labels, float* __restrict__ out, int mode)
{
    const int j = blockIdx.x * blockDim.x + threadIdx.x;
    if (j >= NI) return;
    const size_t base = (size_t)BB * NI * OPS;
    if (mode == 1) {
        out[base + j] = (float)labels[j];
    } else {
        ((long long*)(out + base))[j] = (long long)labels[j];
    }
}

extern "C" void kernel_launch(void* const* d_in, const int* in_sizes, int n_in,
                              void* d_out, int out_size)
{
    const float* emb    = (const float*)d_in[0];
    const float* Ww     = (const float*)d_in[1];
    const float* Wb     = (const float*)d_in[2];
    const float* Gw     = (const float*)d_in[3];
    const float* Gb     = (const float*)d_in[4];
    const int*   li     = (const int*)d_in[5];
    const int*   ri     = (const int*)d_in[6];
    const int*   labels = (const int*)d_in[7];
    float*       out    = (float*)d_out;

    recur_kernel<<<BB / RPC, 256>>>(emb, Ww, Wb, li, ri);

    const int total_quads = BB * NI / 4;                   // 65408
    proj_kernel<<<total_quads / 8, 256>>>(Gw, Gb, out, total_quads); // 8 warps/block

    const long long base = (long long)BB * NI * OPS;
    const long long tail = (long long)out_size - base;
    if (tail == NI)          tail_kernel<<<2, 256>>>(labels, out, 1);
    else if (tail == 2 * NI) tail_kernel<<<2, 256>>>(labels, out, 2);
}

// round 11
// speedup vs baseline: 1.3983x; 1.0811x over previous
#include <cuda_runtime.h>
#include <cstdint>

#define BB   512      // batch
#define LL   512      // leaves
#define EE   128      // emb
#define OPS  5
#define NI   511      // internal nodes
#define RPC  4        // batch rows per CTA

typedef unsigned long long ull;

// scratch: all node embeddings [B][NI][E]  (~134 MB)
__device__ float g_nodes[(size_t)BB * NI * EE];

// ---------------- packed f32x2 helpers ----------------
__device__ __forceinline__ ull pack2(float lo, float hi) {
    ull r;
    asm("mov.b64 %0, {%1, %2};" : "=l"(r) : "f"(lo), "f"(hi));
    return r;
}
__device__ __forceinline__ void fma2(ull& d, ull a, ull b) {
    asm("fma.rn.f32x2 %0, %1, %2, %0;" : "+l"(d) : "l"(a), "l"(b));
}
__device__ __forceinline__ ull add2(ull a, ull b) {
    ull r;
    asm("add.rn.f32x2 %0, %1, %2;" : "=l"(r) : "l"(a), "l"(b));
    return r;
}
__device__ __forceinline__ float2 unpack2(ull v) {
    float2 f;
    asm("mov.b64 {%0, %1}, %2;" : "=f"(f.x), "=f"(f.y) : "l"(v));
    return f;
}

// ---------------- sequential recurrence ----------------
// Warp-sliced broadcast layout at 512 threads = 16 warps (4 warps/SMSP).
// Warp w owns the 16-float K-slice [16w..16w+15] of the 256-float concat
// [cur | leaf] (warps 0-7: cur, 8-15: leaf; Ww row index is uniformly 16w).
// Lane l owns output cols {l, l+32, l+64, l+96}. All 32 lanes read the SAME
// 16B x-chunk -> broadcast = 1 L1 wavefront per LDS.128.
// Per thread-step: 16 LDS.128-bcast + 128 fma2 + 16 STS + 16 LDS (red) +
// 1 output commit (512 outputs = 4 rows x 128 cols). 2 barriers/step.
__global__ void __launch_bounds__(512, 1) recur_kernel(
    const float* __restrict__ emb,   // [B, L, E]
    const float* __restrict__ Ww,    // [2E, E]
    const float* __restrict__ Wb,    // [E]
    const int*   __restrict__ li,    // [NI]
    const int*   __restrict__ ri)    // [NI]
{
    __shared__ __align__(16) float cur[2][RPC][EE];    // double-buffered state
    __shared__ __align__(16) float leafs[2][RPC][EE];  // double-buffered right leaf
    __shared__ __align__(16) float red[16][RPC][EE];   // per-warp partials (32 KB)
    __shared__ int ridx[NI + 1];

    const int t    = threadIdx.x;
    const int wid  = t >> 5;        // warp = K-slice 0..15
    const int lane = t & 31;
    const int b0   = blockIdx.x * RPC;

    // Weight slice: Ww rows 16*wid..+15, cols lane+32c. 32 b64 regs.
    ull w[4][8];
#pragma unroll
    for (int c = 0; c < 4; c++) {
        const int n = lane + 32 * c;
#pragma unroll
        for (int i = 0; i < 8; i++) {
            const int k = 16 * wid + 2 * i;
            w[c][i] = pack2(Ww[(size_t)k * EE + n], Ww[(size_t)(k + 1) * EE + n]);
        }
    }
    // reduce-phase ownership: thread commits exactly one (rrow, rcol)
    const int   rcol  = t & 127;
    const int   rrow  = t >> 7;     // 0..3
    const float biasv = Wb[rcol];

    // right-leaf indices into smem
    for (int j = t; j < NI; j += 512) ridx[j] = ri[j];
    if (t == 0) ridx[NI] = ri[0];   // dummy for prefetch overrun

    // init cur[0] = leaf(left_idx[0]); loader: 4 rows x 128 cols, 1 float each
    const int l0   = li[0];
    const int r_ld = t >> 7;
    const int c_ld = t & 127;
    cur[0][r_ld][c_ld] = emb[((size_t)(b0 + r_ld) * LL + l0) * EE + c_ld];
    __syncthreads();

    // prefetch right leaf for step 0
    float lv = emb[((size_t)(b0 + r_ld) * LL + ridx[0]) * EE + c_ld];

    for (int j = 0; j < NI; j++) {
        const int rb   = j & 1;         // read state buffer
        const int wbuf = rb ^ 1;        // write state buffer
        // commit prefetched leaf; barrier 1 covers leaf + prev cur commits
        leafs[rb][r_ld][c_ld] = lv;
        const int rnext = ridx[j + 1];
        __syncthreads();
        lv = emb[((size_t)(b0 + r_ld) * LL + rnext) * EE + c_ld];

        // ---- phase A: per-warp 16-K-slice partials, broadcast x reads ----
#pragma unroll
        for (int r = 0; r < RPC; r++) {
            const ulonglong2* xs = (wid < 8)
                ? (const ulonglong2*)&cur[rb][r][wid * 16]
                : (const ulonglong2*)&leafs[rb][r][(wid - 8) * 16];
            ull a0[4] = {0ull, 0ull, 0ull, 0ull};
            ull a1[4] = {0ull, 0ull, 0ull, 0ull};
#pragma unroll
            for (int jj = 0; jj < 4; jj++) {
                const ulonglong2 p = xs[jj];        // broadcast: 1 wavefront
#pragma unroll
                for (int c = 0; c < 4; c++) {
                    fma2(a0[c], p.x, w[c][2*jj]);
                    fma2(a1[c], p.y, w[c][2*jj+1]);
                }
            }
#pragma unroll
            for (int c = 0; c < 4; c++) {
                const float2 f = unpack2(add2(a0[c], a1[c]));
                red[wid][r][lane + 32 * c] = f.x + f.y;   // contiguous per warp
            }
        }
        __syncthreads();                 // barrier 2: partials ready

        // ---- phase B: reduce 16 slices, commit 1 output per thread ----
        {
            float s = red[0][rrow][rcol];
#pragma unroll
            for (int sl = 1; sl < 16; sl++) s += red[sl][rrow][rcol];
            const float v = s + biasv;
            cur[wbuf][rrow][rcol] = v;
            g_nodes[((size_t)(b0 + rrow) * NI + j) * EE + rcol] = v;
        }
        // next iteration's barrier 1 orders cur[wbuf] commits vs reads
    }
}

// ---------------- parallel projection: op = node @ G_w + G_b ----------------
// 4 nodes per warp (4 outstanding LDG.128 -> DRAM latency shared)
__global__ void __launch_bounds__(256) proj_kernel(
    const float* __restrict__ Gw,   // [E, OPS]
    const float* __restrict__ Gb,   // [OPS]
    float* __restrict__ out,        // [B, NI, OPS]
    int total_quads)
{
    __shared__ float gws[EE * OPS];
    __shared__ float gbs[OPS];
    const int t = threadIdx.x;
    for (int i = t; i < EE * OPS; i += blockDim.x) gws[i] = Gw[i];
    if (t < OPS) gbs[t] = Gb[t];
    __syncthreads();

    const int quad = blockIdx.x * (blockDim.x >> 5) + (t >> 5);
    if (quad >= total_quads) return;
    const int lane  = t & 31;
    const size_t n0 = (size_t)quad * 4;

    float4 x[4];
#pragma unroll
    for (int q = 0; q < 4; q++)
        x[q] = *(const float4*)&g_nodes[(n0 + q) * EE + lane * 4];
    const float* g = &gws[lane * 4 * OPS];

    float p[4][OPS];
#pragma unroll
    for (int q = 0; q < 4; q++)
#pragma unroll
        for (int o = 0; o < OPS; o++)
            p[q][o] = x[q].x * g[o] + x[q].y * g[OPS + o]
                    + x[q].z * g[2 * OPS + o] + x[q].w * g[3 * OPS + o];

#pragma unroll
    for (int off = 16; off; off >>= 1)
#pragma unroll
        for (int q = 0; q < 4; q++)
#pragma unroll
            for (int o = 0; o < OPS; o++)
                p[q][o] += __shfl_xor_sync(0xFFFFFFFFu, p[q][o], off);

    if (lane == 0) {
        float* op = out + n0 * OPS;
#pragma unroll
        for (int q = 0; q < 4; q++)
#pragma unroll
            for (int o = 0; o < OPS; o++)
                op[q * OPS + o] = p[q][o] + gbs[o];
    }
}

// ---------------- labels tail ----------------
// Labels land on device as int32 (JAX x64 disabled). mode 1: float cast.
// mode 2: widen to raw int64.
__global__ void tail_kernel(const int* __restrict__ labels, float* __restrict__ out, int mode)
{
    const int j = blockIdx.x * blockDim.x + threadIdx.x;
    if (j >= NI) return;
    const size_t base = (size_t)BB * NI * OPS;
    if (mode == 1) {
        out[base + j] = (float)labels[j];
    } else {
        ((long long*)(out + base))[j] = (long long)labels[j];
    }
}

extern "C" void kernel_launch(void* const* d_in, const int* in_sizes, int n_in,
                              void* d_out, int out_size)
{
    const float* emb    = (const float*)d_in[0];
    const float* Ww     = (const float*)d_in[1];
    const float* Wb     = (const float*)d_in[2];
    const float* Gw     = (const float*)d_in[3];
    const float* Gb     = (const float*)d_in[4];
    const int*   li     = (const int*)d_in[5];
    const int*   ri     = (const int*)d_in[6];
    const int*   labels = (const int*)d_in[7];
    float*       out    = (float*)d_out;

    recur_kernel<<<BB / RPC, 512>>>(emb, Ww, Wb, li, ri);

    const int total_quads = BB * NI / 4;                   // 65408
    proj_kernel<<<total_quads / 8, 256>>>(Gw, Gb, out, total_quads); // 8 warps/block

    const long long base = (long long)BB * NI * OPS;
    const long long tail = (long long)out_size - base;
    if (tail == NI)          tail_kernel<<<2, 256>>>(labels, out, 1);
    else if (tail == 2 * NI) tail_kernel<<<2, 256>>>(labels, out, 2);
}